// round 2
// baseline (speedup 1.0000x reference)
#include <cuda_runtime.h>
#include <math.h>

// EnhancedSparseAttention: B=1, C=256, H=W=64 (N=4096), 8 heads, hd=32
// Pipeline:
//  1) q/k/v = W @ x + b           (3x GEMM, output [n][c] layout)
//  2) flash-style masked attention (online softmax, polynomial exp2)
//  3) y2 = x + Wo @ att + bo      (GEMM with residual, output [n][c])
//  4) LayerNorm over channels, write [c][n]
// NOTE: mask arrives as int32 (bool -> int32 harness conversion).

constexpr int CH   = 256;
constexpr int NPIX = 4096;
constexpr int NH   = 8;
constexpr int HD   = 32;

// scratch (no allocation allowed -> device globals)
__device__ float g_q  [NPIX * CH];
__device__ float g_k  [NPIX * CH];
__device__ float g_v  [NPIX * CH];
__device__ float g_att[NPIX * CH];
__device__ float g_y2 [NPIX * CH];

// ---------------------------------------------------------------------------
// Fast exp2 via FFMA polynomial (avoids the 2/SM/cyc MUFU bottleneck).
// Valid for x <= 0 (softmax domain). Clamps at -126 so masked (-1e30) -> ~0.
__device__ __forceinline__ float fexp2(float x) {
    x = fmaxf(x, -126.0f);
    float fl = floorf(x);
    float f  = x - fl;                       // f in [0,1)
    float p  = fmaf(f, 1.5403530e-4f, 1.3333558e-3f);
    p = fmaf(f, p, 9.6181291e-3f);
    p = fmaf(f, p, 5.5504109e-2f);
    p = fmaf(f, p, 2.4022651e-1f);
    p = fmaf(f, p, 6.9314718e-1f);
    p = fmaf(f, p, 1.0f);
    return p * __int_as_float(((int)fl + 127) << 23);
}

// ---------------------------------------------------------------------------
// GEMM: Y[n][o] = sum_c W[o][c] * B[c or n-major] + bias[o] (+ resid[o][n])
// OUTSEL: 0->g_q, 1->g_k, 2->g_v, 3->g_y2
// B_IS_NC: 0 -> B is [c][n] (input x), 1 -> B is [n][c] (g_att)
template<int OUTSEL, int B_IS_NC, int ADD_RES>
__global__ __launch_bounds__(256) void gemm_kernel(
    const float* __restrict__ W, const float* __restrict__ bias,
    const float* __restrict__ Bext, const float* __restrict__ resid)
{
    float* Y = (OUTSEL == 0) ? g_q : (OUTSEL == 1) ? g_k
             : (OUTSEL == 2) ? g_v : g_y2;
    const float* Bp = B_IS_NC ? g_att : Bext;

    __shared__ float Xs[16][68];   // [cc][nn]
    __shared__ float Wt[16][68];   // [cc][oo]

    int t  = threadIdx.x;
    int nb = blockIdx.x * 64;
    int ob = blockIdx.y * 64;
    int nn0 = (t & 15) * 4;
    int oo0 = (t >> 4) * 4;

    float acc[4][4] = {};

    for (int cb = 0; cb < CH; cb += 16) {
        __syncthreads();
        if (B_IS_NC) {
            int cc = t & 15, nnb = t >> 4;
            #pragma unroll
            for (int i = 0; i < 4; i++) {
                int nn = nnb + 16 * i;
                Xs[cc][nn] = Bp[(size_t)(nb + nn) * CH + cb + cc];
            }
        } else {
            int nn = t & 63, ccb = t >> 6;
            #pragma unroll
            for (int i = 0; i < 4; i++) {
                int cc = ccb + 4 * i;
                Xs[cc][nn] = Bp[(size_t)(cb + cc) * NPIX + nb + nn];
            }
        }
        {
            int cc = t & 15, oob = t >> 4;
            #pragma unroll
            for (int i = 0; i < 4; i++) {
                int oo = oob + 16 * i;
                Wt[cc][oo] = W[(size_t)(ob + oo) * CH + cb + cc];
            }
        }
        __syncthreads();

        #pragma unroll
        for (int cc = 0; cc < 16; cc++) {
            float4 xv = *(const float4*)&Xs[cc][nn0];
            float4 wv = *(const float4*)&Wt[cc][oo0];
            float xe[4] = {xv.x, xv.y, xv.z, xv.w};
            float we[4] = {wv.x, wv.y, wv.z, wv.w};
            #pragma unroll
            for (int i = 0; i < 4; i++)
                #pragma unroll
                for (int j = 0; j < 4; j++)
                    acc[i][j] = fmaf(xe[i], we[j], acc[i][j]);
        }
    }

    float4 bv = *(const float4*)&bias[ob + oo0];
    float be[4] = {bv.x, bv.y, bv.z, bv.w};
    #pragma unroll
    for (int i = 0; i < 4; i++) {
        int n = nb + nn0 + i;
        float r[4];
        #pragma unroll
        for (int j = 0; j < 4; j++) {
            r[j] = acc[i][j] + be[j];
            if (ADD_RES)
                r[j] += resid[(size_t)(ob + oo0 + j) * NPIX + n];
        }
        float4 rv = {r[0], r[1], r[2], r[3]};
        *(float4*)&Y[(size_t)n * CH + ob + oo0] = rv;
    }
}

// ---------------------------------------------------------------------------
// Flash-style masked attention.
// Block = one head x 32 query rows; 256 threads (8 warps).
// Warp w owns rows 4w..4w+3 (lanes 0-15: rows 4w,4w+1; lanes 16-31: 4w+2,4w+3).
__global__ __launch_bounds__(256) void attn_kernel(const int* __restrict__ mask)
{
    __shared__ float Qt[32][36];   // [d][row]
    __shared__ float Kt[32][68];   // [d][key]
    __shared__ float Vs[64][32];   // [key][d]

    const unsigned FULL = 0xffffffffu;
    int t    = threadIdx.x;
    int h    = blockIdx.y;
    int qb   = blockIdx.x * 32;
    int lane = t & 31;
    int w    = t >> 5;
    int tr   = t >> 4;
    int tc   = t & 15;
    int r0   = tr * 2;             // local rows r0, r0+1

    // scale * log2(e): softmax done in base-2 domain
    const float qks = 0.17677669529663687f * 1.4426950408889634f;

    {   // load Q tile (reused for all key blocks)
        int d = t & 31, rr = t >> 5;
        #pragma unroll
        for (int i = 0; i < 4; i++) {
            int r = rr + 8 * i;
            Qt[d][r] = g_q[(size_t)(qb + r) * CH + h * HD + d];
        }
    }

    float M0 = -1e30f, M1 = -1e30f, L0 = 0.f, L1 = 0.f;
    float acc0 = 0.f, acc1 = 0.f, acc2 = 0.f, acc3 = 0.f;

    for (int kb = 0; kb < NPIX; kb += 64) {
        __syncthreads();
        {   // load K (transposed) and V tiles
            int d = t & 31, mb = t >> 5;
            #pragma unroll
            for (int i = 0; i < 8; i++) {
                int m = mb + 8 * i;
                size_t gi = (size_t)(kb + m) * CH + h * HD + d;
                Kt[d][m] = g_k[gi];
                Vs[m][d] = g_v[gi];
            }
        }
        __syncthreads();

        // S microtile: 2 rows x 4 keys per thread
        float s00=0,s01=0,s02=0,s03=0,s10=0,s11=0,s12=0,s13=0;
        #pragma unroll
        for (int d = 0; d < 32; d++) {
            float2 qv = *(const float2*)&Qt[d][r0];
            float4 kv = *(const float4*)&Kt[d][tc * 4];
            s00 = fmaf(qv.x, kv.x, s00);
            s01 = fmaf(qv.x, kv.y, s01);
            s02 = fmaf(qv.x, kv.z, s02);
            s03 = fmaf(qv.x, kv.w, s03);
            s10 = fmaf(qv.y, kv.x, s10);
            s11 = fmaf(qv.y, kv.y, s11);
            s12 = fmaf(qv.y, kv.z, s12);
            s13 = fmaf(qv.y, kv.w, s13);
        }

        // mask (int32 elements; 4 per row as one int4, coalesced)
        int4 mw0 = *(const int4*)(mask + ((size_t)(h * NPIX + qb + r0    ) * NPIX + kb + tc * 4));
        int4 mw1 = *(const int4*)(mask + ((size_t)(h * NPIX + qb + r0 + 1) * NPIX + kb + tc * 4));
        s00 = mw0.x ? s00 * qks : -1e30f;
        s01 = mw0.y ? s01 * qks : -1e30f;
        s02 = mw0.z ? s02 * qks : -1e30f;
        s03 = mw0.w ? s03 * qks : -1e30f;
        s10 = mw1.x ? s10 * qks : -1e30f;
        s11 = mw1.y ? s11 * qks : -1e30f;
        s12 = mw1.z ? s12 * qks : -1e30f;
        s13 = mw1.w ? s13 * qks : -1e30f;

        // per-row max across 64 keys (16-lane groups)
        float rm0 = fmaxf(fmaxf(s00, s01), fmaxf(s02, s03));
        float rm1 = fmaxf(fmaxf(s10, s11), fmaxf(s12, s13));
        #pragma unroll
        for (int off = 1; off < 16; off <<= 1) {
            rm0 = fmaxf(rm0, __shfl_xor_sync(FULL, rm0, off));
            rm1 = fmaxf(rm1, __shfl_xor_sync(FULL, rm1, off));
        }
        float Mn0 = fmaxf(M0, rm0), Mn1 = fmaxf(M1, rm1);
        float a0 = fexp2(M0 - Mn0), a1 = fexp2(M1 - Mn1);
        M0 = Mn0; M1 = Mn1;

        float p00 = fexp2(s00 - M0), p01 = fexp2(s01 - M0);
        float p02 = fexp2(s02 - M0), p03 = fexp2(s03 - M0);
        float p10 = fexp2(s10 - M1), p11 = fexp2(s11 - M1);
        float p12 = fexp2(s12 - M1), p13 = fexp2(s13 - M1);

        float ls0 = (p00 + p01) + (p02 + p03);
        float ls1 = (p10 + p11) + (p12 + p13);
        #pragma unroll
        for (int off = 1; off < 16; off <<= 1) {
            ls0 += __shfl_xor_sync(FULL, ls0, off);
            ls1 += __shfl_xor_sync(FULL, ls1, off);
        }
        L0 = fmaf(L0, a0, ls0);
        L1 = fmaf(L1, a1, ls1);

        // broadcast alphas for the warp's 4 rows, rescale d-distributed acc
        float ba0 = __shfl_sync(FULL, a0, 0);
        float ba1 = __shfl_sync(FULL, a1, 0);
        float ba2 = __shfl_sync(FULL, a0, 16);
        float ba3 = __shfl_sync(FULL, a1, 16);
        acc0 *= ba0; acc1 *= ba1; acc2 *= ba2; acc3 *= ba3;

        // P @ V: broadcast p values from owning lanes, FMA with V column
        #pragma unroll
        for (int mo = 0; mo < 16; mo++) {
            #pragma unroll
            for (int jj = 0; jj < 4; jj++) {
                int m = mo * 4 + jj;
                float q0 = (jj == 0) ? p00 : (jj == 1) ? p01 : (jj == 2) ? p02 : p03;
                float q1 = (jj == 0) ? p10 : (jj == 1) ? p11 : (jj == 2) ? p12 : p13;
                float b0 = __shfl_sync(FULL, q0, mo);
                float b1 = __shfl_sync(FULL, q1, mo);
                float b2 = __shfl_sync(FULL, q0, mo + 16);
                float b3 = __shfl_sync(FULL, q1, mo + 16);
                float vv = Vs[m][lane];
                acc0 = fmaf(b0, vv, acc0);
                acc1 = fmaf(b1, vv, acc1);
                acc2 = fmaf(b2, vv, acc2);
                acc3 = fmaf(b3, vv, acc3);
            }
        }
    }

    float l0 = __shfl_sync(FULL, L0, 0);
    float l1 = __shfl_sync(FULL, L1, 0);
    float l2 = __shfl_sync(FULL, L0, 16);
    float l3 = __shfl_sync(FULL, L1, 16);

    int rb = qb + w * 4;
    size_t o = (size_t)rb * CH + h * HD + lane;   // att stored [n][c], coalesced
    g_att[o         ] = acc0 / l0;
    g_att[o +     CH] = acc1 / l1;
    g_att[o + 2 * CH] = acc2 / l2;
    g_att[o + 3 * CH] = acc3 / l3;
}

// ---------------------------------------------------------------------------
// LayerNorm over channels per pixel; reads y2 [n][c], writes out [c][n]
// through an smem transpose so both sides stay coalesced.
__global__ __launch_bounds__(256) void ln_kernel(
    const float* __restrict__ gamma, const float* __restrict__ beta,
    float* __restrict__ out)
{
    __shared__ float tile[32][257];
    __shared__ float mu_s[32], rs_s[32];
    const unsigned FULL = 0xffffffffu;

    int t    = threadIdx.x;
    int pb   = blockIdx.x * 32;
    int lane = t & 31;
    int w    = t >> 5;

    #pragma unroll
    for (int i = 0; i < 32; i++)
        tile[i][t] = g_y2[(size_t)(pb + i) * CH + t];
    __syncthreads();

    #pragma unroll
    for (int pi = 0; pi < 4; pi++) {
        int p = w + 8 * pi;
        float sm = 0.f, sq = 0.f;
        #pragma unroll
        for (int c = 0; c < CH; c += 32) {
            float xv = tile[p][c + lane];
            sm += xv;
            sq  = fmaf(xv, xv, sq);
        }
        #pragma unroll
        for (int off = 16; off > 0; off >>= 1) {
            sm += __shfl_xor_sync(FULL, sm, off);
            sq += __shfl_xor_sync(FULL, sq, off);
        }
        if (lane == 0) {
            float mu  = sm * (1.0f / CH);
            float var = sq * (1.0f / CH) - mu * mu;
            mu_s[p] = mu;
            rs_s[p] = rsqrtf(var + 1e-5f);
        }
    }
    __syncthreads();

    float mu = mu_s[lane];
    float rs = rs_s[lane];
    #pragma unroll
    for (int i = 0; i < 32; i++) {
        int c = w + 8 * i;
        float g = gamma[c], b = beta[c];
        out[(size_t)c * NPIX + pb + lane] = (tile[lane][c] - mu) * rs * g + b;
    }
}

// ---------------------------------------------------------------------------
extern "C" void kernel_launch(void* const* d_in, const int* in_sizes, int n_in,
                              void* d_out, int out_size)
{
    const float* x    = (const float*)d_in[0];
    const int*   mask = (const int*)d_in[1];
    const float* Wq = (const float*)d_in[2];
    const float* bq = (const float*)d_in[3];
    const float* Wk = (const float*)d_in[4];
    const float* bk = (const float*)d_in[5];
    const float* Wv = (const float*)d_in[6];
    const float* bv = (const float*)d_in[7];
    const float* Wo = (const float*)d_in[8];
    const float* bo = (const float*)d_in[9];
    const float* gamma = (const float*)d_in[10];
    const float* beta  = (const float*)d_in[11];
    float* out = (float*)d_out;

    dim3 gg(NPIX / 64, CH / 64);
    gemm_kernel<0, 0, 0><<<gg, 256>>>(Wq, bq, x, nullptr);
    gemm_kernel<1, 0, 0><<<gg, 256>>>(Wk, bk, x, nullptr);
    gemm_kernel<2, 0, 0><<<gg, 256>>>(Wv, bv, x, nullptr);
    attn_kernel<<<dim3(NPIX / 32, NH), 256>>>(mask);
    gemm_kernel<3, 1, 1><<<gg, 256>>>(Wo, bo, nullptr, x);
    ln_kernel<<<NPIX / 32, 256>>>(gamma, beta, out);
}

// round 3
// speedup vs baseline: 2.5095x; 2.5095x over previous
#include <cuda_runtime.h>
#include <math.h>
#include <stdint.h>

// EnhancedSparseAttention: B=1, C=256, H=W=64 (N=4096), 8 heads, hd=32
//  1) q/k/v = W @ x + b            (3x GEMM, output [n][c])
//  2) flash attention, tf32 mma.sync (m16n8k8), online softmax, poly exp2
//  3) y2 = x + Wo @ att + bo       (GEMM with residual)
//  4) LayerNorm over channels, write [c][n]
// mask arrives as int32 (bool -> int32 harness conversion).

constexpr int CH   = 256;
constexpr int NPIX = 4096;
constexpr int NH   = 8;
constexpr int HD   = 32;

__device__ float g_q  [NPIX * CH];
__device__ float g_k  [NPIX * CH];
__device__ float g_v  [NPIX * CH];
__device__ float g_att[NPIX * CH];
__device__ float g_y2 [NPIX * CH];

// ---------------------------------------------------------------------------
// exp2 via FFMA polynomial (x <= 0 domain; clamps so masked -1e30 -> ~0)
__device__ __forceinline__ float fexp2(float x) {
    x = fmaxf(x, -126.0f);
    float fl = floorf(x);
    float f  = x - fl;
    float p  = fmaf(f, 1.5403530e-4f, 1.3333558e-3f);
    p = fmaf(f, p, 9.6181291e-3f);
    p = fmaf(f, p, 5.5504109e-2f);
    p = fmaf(f, p, 2.4022651e-1f);
    p = fmaf(f, p, 6.9314718e-1f);
    p = fmaf(f, p, 1.0f);
    return p * __int_as_float(((int)fl + 127) << 23);
}

__device__ __forceinline__ unsigned f2tf(float x) {
    unsigned u;
    asm("cvt.rna.tf32.f32 %0, %1;" : "=r"(u) : "f"(x));
    return u;
}

__device__ __forceinline__ void mma8(float& c0, float& c1, float& c2, float& c3,
                                     unsigned a0, unsigned a1, unsigned a2, unsigned a3,
                                     unsigned b0, unsigned b1) {
    asm("mma.sync.aligned.m16n8k8.row.col.f32.tf32.tf32.f32 "
        "{%0,%1,%2,%3}, {%4,%5,%6,%7}, {%8,%9}, {%0,%1,%2,%3};"
        : "+f"(c0), "+f"(c1), "+f"(c2), "+f"(c3)
        : "r"(a0), "r"(a1), "r"(a2), "r"(a3), "r"(b0), "r"(b1));
}

// ---------------------------------------------------------------------------
// GEMM: Y[n][o] = sum_c W[o][c] * B + bias[o] (+ resid[o][n])
template<int OUTSEL, int B_IS_NC, int ADD_RES>
__global__ __launch_bounds__(256) void gemm_kernel(
    const float* __restrict__ W, const float* __restrict__ bias,
    const float* __restrict__ Bext, const float* __restrict__ resid)
{
    float* Y = (OUTSEL == 0) ? g_q : (OUTSEL == 1) ? g_k
             : (OUTSEL == 2) ? g_v : g_y2;
    const float* Bp = B_IS_NC ? g_att : Bext;

    __shared__ float Xs[16][68];
    __shared__ float Wt[16][68];

    int t  = threadIdx.x;
    int nb = blockIdx.x * 64;
    int ob = blockIdx.y * 64;
    int nn0 = (t & 15) * 4;
    int oo0 = (t >> 4) * 4;

    float acc[4][4] = {};

    for (int cb = 0; cb < CH; cb += 16) {
        __syncthreads();
        if (B_IS_NC) {
            int cc = t & 15, nnb = t >> 4;
            #pragma unroll
            for (int i = 0; i < 4; i++) {
                int nn = nnb + 16 * i;
                Xs[cc][nn] = Bp[(size_t)(nb + nn) * CH + cb + cc];
            }
        } else {
            int nn = t & 63, ccb = t >> 6;
            #pragma unroll
            for (int i = 0; i < 4; i++) {
                int cc = ccb + 4 * i;
                Xs[cc][nn] = Bp[(size_t)(cb + cc) * NPIX + nb + nn];
            }
        }
        {
            int cc = t & 15, oob = t >> 4;
            #pragma unroll
            for (int i = 0; i < 4; i++) {
                int oo = oob + 16 * i;
                Wt[cc][oo] = W[(size_t)(ob + oo) * CH + cb + cc];
            }
        }
        __syncthreads();

        #pragma unroll
        for (int cc = 0; cc < 16; cc++) {
            float4 xv = *(const float4*)&Xs[cc][nn0];
            float4 wv = *(const float4*)&Wt[cc][oo0];
            float xe[4] = {xv.x, xv.y, xv.z, xv.w};
            float we[4] = {wv.x, wv.y, wv.z, wv.w};
            #pragma unroll
            for (int i = 0; i < 4; i++)
                #pragma unroll
                for (int j = 0; j < 4; j++)
                    acc[i][j] = fmaf(xe[i], we[j], acc[i][j]);
        }
    }

    float4 bv = *(const float4*)&bias[ob + oo0];
    float be[4] = {bv.x, bv.y, bv.z, bv.w};
    #pragma unroll
    for (int i = 0; i < 4; i++) {
        int n = nb + nn0 + i;
        float r[4];
        #pragma unroll
        for (int j = 0; j < 4; j++) {
            r[j] = acc[i][j] + be[j];
            if (ADD_RES)
                r[j] += resid[(size_t)(ob + oo0 + j) * NPIX + n];
        }
        float4 rv = {r[0], r[1], r[2], r[3]};
        *(float4*)&Y[(size_t)n * CH + ob + oo0] = rv;
    }
}

// ---------------------------------------------------------------------------
// Flash attention with tf32 mma.sync.
// CTA: 1 head x 64 query rows, 128 threads (4 warps); warp w = rows 16w..16w+15.
// Key blocks of 64. K staged [key][36] tf32, V staged [key][40] tf32
// (strides chosen so B-fragment scalar LDS are bank-conflict-free).
__global__ __launch_bounds__(128) void attn_kernel(const int* __restrict__ mask)
{
    __shared__ unsigned Kd[64][36];
    __shared__ unsigned Vs[64][40];

    const unsigned F = 0xffffffffu;
    int t    = threadIdx.x;
    int lane = t & 31;
    int w    = t >> 5;
    int h    = blockIdx.y;
    int qb   = blockIdx.x * 64;
    int gr   = lane >> 2;    // 0..7  (fragment row group)
    int qt   = lane & 3;     // 0..3  (quad thread)

    const float qks = 0.17677669529663687f * 1.4426950408889634f; // scale*log2e

    int r_lo = qb + w * 16 + gr;
    int r_hi = r_lo + 8;

    // Q fragments, pre-scaled, tf32, resident for the whole kernel
    unsigned qf[4][4];
    #pragma unroll
    for (int kk = 0; kk < 4; kk++) {
        int d0 = kk * 8 + qt;
        qf[kk][0] = f2tf(qks * g_q[(size_t)r_lo * CH + h * HD + d0]);
        qf[kk][1] = f2tf(qks * g_q[(size_t)r_hi * CH + h * HD + d0]);
        qf[kk][2] = f2tf(qks * g_q[(size_t)r_lo * CH + h * HD + d0 + 4]);
        qf[kk][3] = f2tf(qks * g_q[(size_t)r_hi * CH + h * HD + d0 + 4]);
    }

    float oc[4][4] = {};                 // O accumulators [dt][c-frag]
    float M0 = -1e30f, M1 = -1e30f, L0 = 0.f, L1 = 0.f;

    const size_t mrow_lo = ((size_t)h * NPIX + r_lo) * NPIX;
    const size_t mrow_hi = ((size_t)h * NPIX + r_hi) * NPIX;

    for (int kb = 0; kb < NPIX; kb += 64) {
        __syncthreads();
        {   // stage K,V -> smem (tf32); lane=d, warp owns keys == w (mod 4)
            int d = lane;
            #pragma unroll
            for (int i = 0; i < 16; i++) {
                int key = w + 4 * i;
                size_t gi = (size_t)(kb + key) * CH + h * HD + d;
                Kd[key][d] = f2tf(g_k[gi]);
                Vs[key][d] = f2tf(g_v[gi]);
            }
        }
        __syncthreads();

        // mask prefetch: int2 per (row, n-tile); cols 2qt,2qt+1 match c0,c1
        int2 mw0[8], mw1[8];
        #pragma unroll
        for (int nt = 0; nt < 8; nt++) {
            size_t c = (size_t)(kb + nt * 8 + 2 * qt);
            mw0[nt] = *(const int2*)(mask + mrow_lo + c);
            mw1[nt] = *(const int2*)(mask + mrow_hi + c);
        }

        // S = (qks*Q) K^T via mma; apply mask
        float sc[8][4];
        #pragma unroll
        for (int nt = 0; nt < 8; nt++) {
            float c0 = 0.f, c1 = 0.f, c2 = 0.f, c3 = 0.f;
            #pragma unroll
            for (int kk = 0; kk < 4; kk++) {
                unsigned b0 = Kd[nt * 8 + gr][kk * 8 + qt];
                unsigned b1 = Kd[nt * 8 + gr][kk * 8 + qt + 4];
                mma8(c0, c1, c2, c3,
                     qf[kk][0], qf[kk][1], qf[kk][2], qf[kk][3], b0, b1);
            }
            sc[nt][0] = mw0[nt].x ? c0 : -1e30f;
            sc[nt][1] = mw0[nt].y ? c1 : -1e30f;
            sc[nt][2] = mw1[nt].x ? c2 : -1e30f;
            sc[nt][3] = mw1[nt].y ? c3 : -1e30f;
        }

        // online softmax (rows r_lo -> c0/c1, r_hi -> c2/c3)
        float m_lo = -1e30f, m_hi = -1e30f;
        #pragma unroll
        for (int nt = 0; nt < 8; nt++) {
            m_lo = fmaxf(m_lo, fmaxf(sc[nt][0], sc[nt][1]));
            m_hi = fmaxf(m_hi, fmaxf(sc[nt][2], sc[nt][3]));
        }
        m_lo = fmaxf(m_lo, __shfl_xor_sync(F, m_lo, 1));
        m_lo = fmaxf(m_lo, __shfl_xor_sync(F, m_lo, 2));
        m_hi = fmaxf(m_hi, __shfl_xor_sync(F, m_hi, 1));
        m_hi = fmaxf(m_hi, __shfl_xor_sync(F, m_hi, 2));

        float Mn0 = fmaxf(M0, m_lo), Mn1 = fmaxf(M1, m_hi);
        float a0 = fexp2(M0 - Mn0), a1 = fexp2(M1 - Mn1);
        M0 = Mn0; M1 = Mn1;

        float ls0 = 0.f, ls1 = 0.f;
        #pragma unroll
        for (int nt = 0; nt < 8; nt++) {
            sc[nt][0] = fexp2(sc[nt][0] - M0);
            sc[nt][1] = fexp2(sc[nt][1] - M0);
            sc[nt][2] = fexp2(sc[nt][2] - M1);
            sc[nt][3] = fexp2(sc[nt][3] - M1);
            ls0 += sc[nt][0] + sc[nt][1];
            ls1 += sc[nt][2] + sc[nt][3];
        }
        ls0 += __shfl_xor_sync(F, ls0, 1);
        ls0 += __shfl_xor_sync(F, ls0, 2);
        ls1 += __shfl_xor_sync(F, ls1, 1);
        ls1 += __shfl_xor_sync(F, ls1, 2);
        L0 = fmaf(L0, a0, ls0);
        L1 = fmaf(L1, a1, ls1);

        #pragma unroll
        for (int dt = 0; dt < 4; dt++) {
            oc[dt][0] *= a0; oc[dt][1] *= a0;
            oc[dt][2] *= a1; oc[dt][3] *= a1;
        }

        // P -> tf32 bit patterns (kept in float regs for shfl)
        #pragma unroll
        for (int nt = 0; nt < 8; nt++)
            #pragma unroll
            for (int i = 0; i < 4; i++)
                sc[nt][i] = __uint_as_float(f2tf(sc[nt][i]));

        // O += P V   (A-fragments of P built via quad shuffles)
        int s_lo = (lane & ~3) | (qt >> 1);
        int s_hi = s_lo + 2;
        bool odd = (lane & 1);
        #pragma unroll
        for (int kk = 0; kk < 8; kk++) {
            float v0 = __shfl_sync(F, sc[kk][0], s_lo);
            float v1 = __shfl_sync(F, sc[kk][1], s_lo);
            float v2 = __shfl_sync(F, sc[kk][2], s_lo);
            float v3 = __shfl_sync(F, sc[kk][3], s_lo);
            float u0 = __shfl_sync(F, sc[kk][0], s_hi);
            float u1 = __shfl_sync(F, sc[kk][1], s_hi);
            float u2 = __shfl_sync(F, sc[kk][2], s_hi);
            float u3 = __shfl_sync(F, sc[kk][3], s_hi);
            unsigned a0u = __float_as_uint(odd ? v1 : v0);
            unsigned a1u = __float_as_uint(odd ? v3 : v2);
            unsigned a2u = __float_as_uint(odd ? u1 : u0);
            unsigned a3u = __float_as_uint(odd ? u3 : u2);
            #pragma unroll
            for (int dt = 0; dt < 4; dt++) {
                unsigned b0 = Vs[kk * 8 + qt][dt * 8 + gr];
                unsigned b1 = Vs[kk * 8 + qt + 4][dt * 8 + gr];
                mma8(oc[dt][0], oc[dt][1], oc[dt][2], oc[dt][3],
                     a0u, a1u, a2u, a3u, b0, b1);
            }
        }
    }

    float rl0 = 1.0f / L0;
    float rl1 = 1.0f / L1;
    #pragma unroll
    for (int dt = 0; dt < 4; dt++) {
        int cb = h * HD + dt * 8 + 2 * qt;
        float2 vlo = { oc[dt][0] * rl0, oc[dt][1] * rl0 };
        float2 vhi = { oc[dt][2] * rl1, oc[dt][3] * rl1 };
        *(float2*)&g_att[(size_t)r_lo * CH + cb] = vlo;
        *(float2*)&g_att[(size_t)r_hi * CH + cb] = vhi;
    }
}

// ---------------------------------------------------------------------------
// LayerNorm over channels per pixel; reads y2 [n][c], writes out [c][n]
__global__ __launch_bounds__(256) void ln_kernel(
    const float* __restrict__ gamma, const float* __restrict__ beta,
    float* __restrict__ out)
{
    __shared__ float tile[32][257];
    __shared__ float mu_s[32], rs_s[32];
    const unsigned FULL = 0xffffffffu;

    int t    = threadIdx.x;
    int pb   = blockIdx.x * 32;
    int lane = t & 31;
    int w    = t >> 5;

    #pragma unroll
    for (int i = 0; i < 32; i++)
        tile[i][t] = g_y2[(size_t)(pb + i) * CH + t];
    __syncthreads();

    #pragma unroll
    for (int pi = 0; pi < 4; pi++) {
        int p = w + 8 * pi;
        float sm = 0.f, sq = 0.f;
        #pragma unroll
        for (int c = 0; c < CH; c += 32) {
            float xv = tile[p][c + lane];
            sm += xv;
            sq  = fmaf(xv, xv, sq);
        }
        #pragma unroll
        for (int off = 16; off > 0; off >>= 1) {
            sm += __shfl_xor_sync(FULL, sm, off);
            sq += __shfl_xor_sync(FULL, sq, off);
        }
        if (lane == 0) {
            float mu  = sm * (1.0f / CH);
            float var = sq * (1.0f / CH) - mu * mu;
            mu_s[p] = mu;
            rs_s[p] = rsqrtf(var + 1e-5f);
        }
    }
    __syncthreads();

    float mu = mu_s[lane];
    float rs = rs_s[lane];
    #pragma unroll
    for (int i = 0; i < 32; i++) {
        int c = w + 8 * i;
        float g = gamma[c], b = beta[c];
        out[(size_t)c * NPIX + pb + lane] = (tile[lane][c] - mu) * rs * g + b;
    }
}

// ---------------------------------------------------------------------------
extern "C" void kernel_launch(void* const* d_in, const int* in_sizes, int n_in,
                              void* d_out, int out_size)
{
    const float* x    = (const float*)d_in[0];
    const int*   mask = (const int*)d_in[1];
    const float* Wq = (const float*)d_in[2];
    const float* bq = (const float*)d_in[3];
    const float* Wk = (const float*)d_in[4];
    const float* bk = (const float*)d_in[5];
    const float* Wv = (const float*)d_in[6];
    const float* bv = (const float*)d_in[7];
    const float* Wo = (const float*)d_in[8];
    const float* bo = (const float*)d_in[9];
    const float* gamma = (const float*)d_in[10];
    const float* beta  = (const float*)d_in[11];
    float* out = (float*)d_out;

    dim3 gg(NPIX / 64, CH / 64);
    gemm_kernel<0, 0, 0><<<gg, 256>>>(Wq, bq, x, nullptr);
    gemm_kernel<1, 0, 0><<<gg, 256>>>(Wk, bk, x, nullptr);
    gemm_kernel<2, 0, 0><<<gg, 256>>>(Wv, bv, x, nullptr);
    attn_kernel<<<dim3(NPIX / 64, NH), 128>>>(mask);
    gemm_kernel<3, 1, 1><<<gg, 256>>>(Wo, bo, nullptr, x);
    ln_kernel<<<NPIX / 32, 256>>>(gamma, beta, out);
}

// round 4
// speedup vs baseline: 3.1765x; 1.2658x over previous
#include <cuda_runtime.h>
#include <math.h>
#include <stdint.h>

// EnhancedSparseAttention: B=1, C=256, H=W=64 (N=4096), 8 heads, hd=32
//  1) q/k/v = W @ x + b            (merged GEMM, output [n][c])
//  2) flash attention: QK^T tf32 mma, PV fp16 mma (layout-matched, no shuffles),
//     online softmax w/ polynomial exp2, reg-prefetch K/V pipeline
//  3) y2 = x + Wo @ att + bo       (GEMM with residual)
//  4) LayerNorm over channels, write [c][n]
// mask arrives as int32 (bool -> int32 harness conversion).

constexpr int CH   = 256;
constexpr int NPIX = 4096;
constexpr int NH   = 8;
constexpr int HD   = 32;

__device__ float g_q  [NPIX * CH];
__device__ float g_k  [NPIX * CH];
__device__ float g_v  [NPIX * CH];
__device__ float g_att[NPIX * CH];
__device__ float g_y2 [NPIX * CH];

// ---------------------------------------------------------------------------
__device__ __forceinline__ float fexp2(float x) {
    x = fmaxf(x, -126.0f);
    float fl = floorf(x);
    float f  = x - fl;
    float p  = fmaf(f, 1.5403530e-4f, 1.3333558e-3f);
    p = fmaf(f, p, 9.6181291e-3f);
    p = fmaf(f, p, 5.5504109e-2f);
    p = fmaf(f, p, 2.4022651e-1f);
    p = fmaf(f, p, 6.9314718e-1f);
    p = fmaf(f, p, 1.0f);
    return p * __int_as_float(((int)fl + 127) << 23);
}

__device__ __forceinline__ unsigned f2tf(float x) {
    unsigned u;
    asm("cvt.rna.tf32.f32 %0, %1;" : "=r"(u) : "f"(x));
    return u;
}

// pack two f32 -> f16x2 (lo in low half)
__device__ __forceinline__ unsigned pkh2(float lo, float hi) {
    unsigned r;
    asm("cvt.rn.f16x2.f32 %0, %1, %2;" : "=r"(r) : "f"(hi), "f"(lo));
    return r;
}

__device__ __forceinline__ void mma8(float& c0, float& c1, float& c2, float& c3,
                                     unsigned a0, unsigned a1, unsigned a2, unsigned a3,
                                     unsigned b0, unsigned b1) {
    asm("mma.sync.aligned.m16n8k8.row.col.f32.tf32.tf32.f32 "
        "{%0,%1,%2,%3}, {%4,%5,%6,%7}, {%8,%9}, {%0,%1,%2,%3};"
        : "+f"(c0), "+f"(c1), "+f"(c2), "+f"(c3)
        : "r"(a0), "r"(a1), "r"(a2), "r"(a3), "r"(b0), "r"(b1));
}

__device__ __forceinline__ void mma16h(float& c0, float& c1, float& c2, float& c3,
                                       unsigned a0, unsigned a1, unsigned a2, unsigned a3,
                                       unsigned b0, unsigned b1) {
    asm("mma.sync.aligned.m16n8k16.row.col.f32.f16.f16.f32 "
        "{%0,%1,%2,%3}, {%4,%5,%6,%7}, {%8,%9}, {%0,%1,%2,%3};"
        : "+f"(c0), "+f"(c1), "+f"(c2), "+f"(c3)
        : "r"(a0), "r"(a1), "r"(a2), "r"(a3), "r"(b0), "r"(b1));
}

// ---------------------------------------------------------------------------
// Merged QKV GEMM: grid (NPIX/64, 12); blockIdx.y>>2 selects q/k/v, &3 -> ob.
__global__ __launch_bounds__(256) void gemm_qkv(
    const float* __restrict__ x,
    const float* __restrict__ Wq, const float* __restrict__ bq,
    const float* __restrict__ Wk, const float* __restrict__ bk,
    const float* __restrict__ Wv, const float* __restrict__ bv)
{
    int sel = blockIdx.y >> 2;
    const float* W    = (sel == 0) ? Wq : (sel == 1) ? Wk : Wv;
    const float* bias = (sel == 0) ? bq : (sel == 1) ? bk : bv;
    float* Y          = (sel == 0) ? g_q : (sel == 1) ? g_k : g_v;

    __shared__ float Xs[16][68];
    __shared__ float Wt[16][68];

    int t  = threadIdx.x;
    int nb = blockIdx.x * 64;
    int ob = (blockIdx.y & 3) * 64;
    int nn0 = (t & 15) * 4;
    int oo0 = (t >> 4) * 4;

    float acc[4][4] = {};

    for (int cb = 0; cb < CH; cb += 16) {
        __syncthreads();
        {
            int nn = t & 63, ccb = t >> 6;
            #pragma unroll
            for (int i = 0; i < 4; i++) {
                int cc = ccb + 4 * i;
                Xs[cc][nn] = x[(size_t)(cb + cc) * NPIX + nb + nn];
            }
        }
        {
            int cc = t & 15, oob = t >> 4;
            #pragma unroll
            for (int i = 0; i < 4; i++) {
                int oo = oob + 16 * i;
                Wt[cc][oo] = W[(size_t)(ob + oo) * CH + cb + cc];
            }
        }
        __syncthreads();

        #pragma unroll
        for (int cc = 0; cc < 16; cc++) {
            float4 xv = *(const float4*)&Xs[cc][nn0];
            float4 wv = *(const float4*)&Wt[cc][oo0];
            float xe[4] = {xv.x, xv.y, xv.z, xv.w};
            float we[4] = {wv.x, wv.y, wv.z, wv.w};
            #pragma unroll
            for (int i = 0; i < 4; i++)
                #pragma unroll
                for (int j = 0; j < 4; j++)
                    acc[i][j] = fmaf(xe[i], we[j], acc[i][j]);
        }
    }

    float4 bv2 = *(const float4*)&bias[ob + oo0];
    float be[4] = {bv2.x, bv2.y, bv2.z, bv2.w};
    #pragma unroll
    for (int i = 0; i < 4; i++) {
        int n = nb + nn0 + i;
        float4 rv = { acc[i][0] + be[0], acc[i][1] + be[1],
                      acc[i][2] + be[2], acc[i][3] + be[3] };
        *(float4*)&Y[(size_t)n * CH + ob + oo0] = rv;
    }
}

// Output GEMM with residual: y2[n][o] = sum_c Wo[o][c]*att[n][c] + bo + x[o][n]
__global__ __launch_bounds__(256) void gemm_o(
    const float* __restrict__ W, const float* __restrict__ bias,
    const float* __restrict__ resid)
{
    __shared__ float Xs[16][68];
    __shared__ float Wt[16][68];

    int t  = threadIdx.x;
    int nb = blockIdx.x * 64;
    int ob = blockIdx.y * 64;
    int nn0 = (t & 15) * 4;
    int oo0 = (t >> 4) * 4;

    float acc[4][4] = {};

    for (int cb = 0; cb < CH; cb += 16) {
        __syncthreads();
        {
            int cc = t & 15, nnb = t >> 4;
            #pragma unroll
            for (int i = 0; i < 4; i++) {
                int nn = nnb + 16 * i;
                Xs[cc][nn] = g_att[(size_t)(nb + nn) * CH + cb + cc];
            }
        }
        {
            int cc = t & 15, oob = t >> 4;
            #pragma unroll
            for (int i = 0; i < 4; i++) {
                int oo = oob + 16 * i;
                Wt[cc][oo] = W[(size_t)(ob + oo) * CH + cb + cc];
            }
        }
        __syncthreads();

        #pragma unroll
        for (int cc = 0; cc < 16; cc++) {
            float4 xv = *(const float4*)&Xs[cc][nn0];
            float4 wv = *(const float4*)&Wt[cc][oo0];
            float xe[4] = {xv.x, xv.y, xv.z, xv.w};
            float we[4] = {wv.x, wv.y, wv.z, wv.w};
            #pragma unroll
            for (int i = 0; i < 4; i++)
                #pragma unroll
                for (int j = 0; j < 4; j++)
                    acc[i][j] = fmaf(xe[i], we[j], acc[i][j]);
        }
    }

    float4 bv = *(const float4*)&bias[ob + oo0];
    float be[4] = {bv.x, bv.y, bv.z, bv.w};
    #pragma unroll
    for (int i = 0; i < 4; i++) {
        int n = nb + nn0 + i;
        float r[4];
        #pragma unroll
        for (int j = 0; j < 4; j++)
            r[j] = acc[i][j] + be[j] + resid[(size_t)(ob + oo0 + j) * NPIX + n];
        float4 rv = {r[0], r[1], r[2], r[3]};
        *(float4*)&g_y2[(size_t)n * CH + ob + oo0] = rv;
    }
}

// ---------------------------------------------------------------------------
// Flash attention. CTA: 1 head x 64 q-rows, 4 warps (16 rows each).
// QK^T: tf32 m16n8k8 (K staged [key][36] tf32).
// PV:   fp16 m16n8k16; S C-frag layout == fp16 A-frag layout -> no shuffles.
//       V staged as half2 key-pairs [d][pair], stride 36 (conflict-free).
// K/V prefetched into registers one block ahead.
__global__ __launch_bounds__(128, 4) void attn_kernel(const int* __restrict__ mask)
{
    __shared__ unsigned Kd[64][36];
    __shared__ unsigned Vh2[32][36];

    const unsigned F = 0xffffffffu;
    int t    = threadIdx.x;
    int lane = t & 31;
    int w    = t >> 5;
    int h    = blockIdx.y;
    int qb   = blockIdx.x * 64;
    int gr   = lane >> 2;
    int qt   = lane & 3;
    int hoff = h * HD;

    const float qks = 0.17677669529663687f * 1.4426950408889634f;

    int r_lo = qb + w * 16 + gr;
    int r_hi = r_lo + 8;

    unsigned qf[4][4];
    #pragma unroll
    for (int kk = 0; kk < 4; kk++) {
        int d0 = kk * 8 + qt;
        qf[kk][0] = f2tf(qks * g_q[(size_t)r_lo * CH + hoff + d0]);
        qf[kk][1] = f2tf(qks * g_q[(size_t)r_hi * CH + hoff + d0]);
        qf[kk][2] = f2tf(qks * g_q[(size_t)r_lo * CH + hoff + d0 + 4]);
        qf[kk][3] = f2tf(qks * g_q[(size_t)r_hi * CH + hoff + d0 + 4]);
    }

    float oc[4][4] = {};
    float M0 = -1e30f, M1 = -1e30f, L0 = 0.f, L1 = 0.f;

    const size_t mrow_lo = ((size_t)h * NPIX + r_lo) * NPIX;
    const size_t mrow_hi = ((size_t)h * NPIX + r_hi) * NPIX;

    // prefetch registers: K keys w+4i (i 0..15); V keys 8u..8u+7, u in {w, w+4}
    float kpf[16], vpf[16];
    #pragma unroll
    for (int i = 0; i < 16; i++)
        kpf[i] = g_k[(size_t)(w + 4 * i) * CH + hoff + lane];
    #pragma unroll
    for (int i = 0; i < 2; i++) {
        int u = w + 4 * i;
        #pragma unroll
        for (int j = 0; j < 8; j++)
            vpf[i * 8 + j] = g_v[(size_t)(8 * u + j) * CH + hoff + lane];
    }

    for (int kb = 0; kb < NPIX; kb += 64) {
        __syncthreads();   // previous block's smem reads done
        {
            int d = lane;
            #pragma unroll
            for (int i = 0; i < 16; i++)
                Kd[w + 4 * i][d] = f2tf(kpf[i]);
            #pragma unroll
            for (int i = 0; i < 2; i++) {
                int u = w + 4 * i;
                uint4 pk;
                pk.x = pkh2(vpf[i * 8 + 0], vpf[i * 8 + 1]);
                pk.y = pkh2(vpf[i * 8 + 2], vpf[i * 8 + 3]);
                pk.z = pkh2(vpf[i * 8 + 4], vpf[i * 8 + 5]);
                pk.w = pkh2(vpf[i * 8 + 6], vpf[i * 8 + 7]);
                *(uint4*)&Vh2[d][4 * u] = pk;
            }
        }
        __syncthreads();

        if (kb + 64 < NPIX) {   // prefetch next block while computing this one
            int nb2 = kb + 64;
            #pragma unroll
            for (int i = 0; i < 16; i++)
                kpf[i] = g_k[(size_t)(nb2 + w + 4 * i) * CH + hoff + lane];
            #pragma unroll
            for (int i = 0; i < 2; i++) {
                int u = w + 4 * i;
                #pragma unroll
                for (int j = 0; j < 8; j++)
                    vpf[i * 8 + j] = g_v[(size_t)(nb2 + 8 * u + j) * CH + hoff + lane];
            }
        }

        // mask prefetch
        int2 mw0[8], mw1[8];
        #pragma unroll
        for (int nt = 0; nt < 8; nt++) {
            size_t c = (size_t)(kb + nt * 8 + 2 * qt);
            mw0[nt] = *(const int2*)(mask + mrow_lo + c);
            mw1[nt] = *(const int2*)(mask + mrow_hi + c);
        }

        // S = (qks*Q) K^T
        float sc[8][4];
        #pragma unroll
        for (int nt = 0; nt < 8; nt++) {
            float c0 = 0.f, c1 = 0.f, c2 = 0.f, c3 = 0.f;
            #pragma unroll
            for (int kk = 0; kk < 4; kk++) {
                unsigned b0 = Kd[nt * 8 + gr][kk * 8 + qt];
                unsigned b1 = Kd[nt * 8 + gr][kk * 8 + qt + 4];
                mma8(c0, c1, c2, c3,
                     qf[kk][0], qf[kk][1], qf[kk][2], qf[kk][3], b0, b1);
            }
            sc[nt][0] = mw0[nt].x ? c0 : -1e30f;
            sc[nt][1] = mw0[nt].y ? c1 : -1e30f;
            sc[nt][2] = mw1[nt].x ? c2 : -1e30f;
            sc[nt][3] = mw1[nt].y ? c3 : -1e30f;
        }

        // online softmax
        float m_lo = -1e30f, m_hi = -1e30f;
        #pragma unroll
        for (int nt = 0; nt < 8; nt++) {
            m_lo = fmaxf(m_lo, fmaxf(sc[nt][0], sc[nt][1]));
            m_hi = fmaxf(m_hi, fmaxf(sc[nt][2], sc[nt][3]));
        }
        m_lo = fmaxf(m_lo, __shfl_xor_sync(F, m_lo, 1));
        m_lo = fmaxf(m_lo, __shfl_xor_sync(F, m_lo, 2));
        m_hi = fmaxf(m_hi, __shfl_xor_sync(F, m_hi, 1));
        m_hi = fmaxf(m_hi, __shfl_xor_sync(F, m_hi, 2));

        float Mn0 = fmaxf(M0, m_lo), Mn1 = fmaxf(M1, m_hi);
        float a0 = fexp2(M0 - Mn0), a1 = fexp2(M1 - Mn1);
        M0 = Mn0; M1 = Mn1;

        float ls0 = 0.f, ls1 = 0.f;
        #pragma unroll
        for (int nt = 0; nt < 8; nt++) {
            sc[nt][0] = fexp2(sc[nt][0] - M0);   // masked -> 2^-126, fp16 -> 0
            sc[nt][1] = fexp2(sc[nt][1] - M0);
            sc[nt][2] = fexp2(sc[nt][2] - M1);
            sc[nt][3] = fexp2(sc[nt][3] - M1);
            ls0 += sc[nt][0] + sc[nt][1];
            ls1 += sc[nt][2] + sc[nt][3];
        }
        L0 = fmaf(L0, a0, ls0);
        L1 = fmaf(L1, a1, ls1);

        #pragma unroll
        for (int dt = 0; dt < 4; dt++) {
            oc[dt][0] *= a0; oc[dt][1] *= a0;
            oc[dt][2] *= a1; oc[dt][3] *= a1;
        }

        // O += P V : fp16 m16n8k16, A-fragments straight from sc (no shuffles)
        #pragma unroll
        for (int j = 0; j < 4; j++) {
            unsigned a0u = pkh2(sc[2*j][0],   sc[2*j][1]);
            unsigned a1u = pkh2(sc[2*j][2],   sc[2*j][3]);
            unsigned a2u = pkh2(sc[2*j+1][0], sc[2*j+1][1]);
            unsigned a3u = pkh2(sc[2*j+1][2], sc[2*j+1][3]);
            #pragma unroll
            for (int dt = 0; dt < 4; dt++) {
                unsigned b0 = Vh2[dt * 8 + gr][8 * j + qt];
                unsigned b1 = Vh2[dt * 8 + gr][8 * j + qt + 4];
                mma16h(oc[dt][0], oc[dt][1], oc[dt][2], oc[dt][3],
                       a0u, a1u, a2u, a3u, b0, b1);
            }
        }
    }

    // finish L reduction across quad
    L0 += __shfl_xor_sync(F, L0, 1);
    L0 += __shfl_xor_sync(F, L0, 2);
    L1 += __shfl_xor_sync(F, L1, 1);
    L1 += __shfl_xor_sync(F, L1, 2);
    // NOTE: each quad-thread accumulated its own partial ls; after xor-reduce
    // all hold full row sum only if partials were disjoint -- they are (cols 2qt,2qt+1).

    float rl0 = 1.0f / L0;
    float rl1 = 1.0f / L1;
    #pragma unroll
    for (int dt = 0; dt < 4; dt++) {
        int cb = hoff + dt * 8 + 2 * qt;
        float2 vlo = { oc[dt][0] * rl0, oc[dt][1] * rl0 };
        float2 vhi = { oc[dt][2] * rl1, oc[dt][3] * rl1 };
        *(float2*)&g_att[(size_t)r_lo * CH + cb] = vlo;
        *(float2*)&g_att[(size_t)r_hi * CH + cb] = vhi;
    }
}

// ---------------------------------------------------------------------------
__global__ __launch_bounds__(256) void ln_kernel(
    const float* __restrict__ gamma, const float* __restrict__ beta,
    float* __restrict__ out)
{
    __shared__ float tile[32][257];
    __shared__ float mu_s[32], rs_s[32];
    const unsigned FULL = 0xffffffffu;

    int t    = threadIdx.x;
    int pb   = blockIdx.x * 32;
    int lane = t & 31;
    int w    = t >> 5;

    #pragma unroll
    for (int i = 0; i < 32; i++)
        tile[i][t] = g_y2[(size_t)(pb + i) * CH + t];
    __syncthreads();

    #pragma unroll
    for (int pi = 0; pi < 4; pi++) {
        int p = w + 8 * pi;
        float sm = 0.f, sq = 0.f;
        #pragma unroll
        for (int c = 0; c < CH; c += 32) {
            float xv = tile[p][c + lane];
            sm += xv;
            sq  = fmaf(xv, xv, sq);
        }
        #pragma unroll
        for (int off = 16; off > 0; off >>= 1) {
            sm += __shfl_xor_sync(FULL, sm, off);
            sq += __shfl_xor_sync(FULL, sq, off);
        }
        if (lane == 0) {
            float mu  = sm * (1.0f / CH);
            float var = sq * (1.0f / CH) - mu * mu;
            mu_s[p] = mu;
            rs_s[p] = rsqrtf(var + 1e-5f);
        }
    }
    __syncthreads();

    float mu = mu_s[lane];
    float rs = rs_s[lane];
    #pragma unroll
    for (int i = 0; i < 32; i++) {
        int c = w + 8 * i;
        float g = gamma[c], b = beta[c];
        out[(size_t)c * NPIX + pb + lane] = (tile[lane][c] - mu) * rs * g + b;
    }
}

// ---------------------------------------------------------------------------
extern "C" void kernel_launch(void* const* d_in, const int* in_sizes, int n_in,
                              void* d_out, int out_size)
{
    const float* x    = (const float*)d_in[0];
    const int*   mask = (const int*)d_in[1];
    const float* Wq = (const float*)d_in[2];
    const float* bq = (const float*)d_in[3];
    const float* Wk = (const float*)d_in[4];
    const float* bk = (const float*)d_in[5];
    const float* Wv = (const float*)d_in[6];
    const float* bv = (const float*)d_in[7];
    const float* Wo = (const float*)d_in[8];
    const float* bo = (const float*)d_in[9];
    const float* gamma = (const float*)d_in[10];
    const float* beta  = (const float*)d_in[11];
    float* out = (float*)d_out;

    gemm_qkv<<<dim3(NPIX / 64, 12), 256>>>(x, Wq, bq, Wk, bk, Wv, bv);
    attn_kernel<<<dim3(NPIX / 64, NH), 128>>>(mask);
    gemm_o<<<dim3(NPIX / 64, CH / 64), 256>>>(Wo, bo, x);
    ln_kernel<<<NPIX / 32, 256>>>(gamma, beta, out);
}

// round 5
// speedup vs baseline: 4.7862x; 1.5068x over previous
#include <cuda_runtime.h>
#include <cuda_fp16.h>
#include <math.h>
#include <stdint.h>

// EnhancedSparseAttention: B=1, C=256, H=W=64 (N=4096), 8 heads, hd=32
//  1) q/k/v = W @ x + b       merged GEMM -> fp16 [n][c] (q pre-scaled by scale*log2e)
//  2) flash attention, all-fp16 mma m16n8k16, ldmatrix B-frags, cp.async double buffer
//  3) y2 = x + Wo @ att + bo  (fp32 GEMM with residual)
//  4) LayerNorm over channels, write [c][n]
// mask arrives as int32 (bool -> int32 harness conversion).

constexpr int CH   = 256;
constexpr int NPIX = 4096;
constexpr int NH   = 8;
constexpr int HD   = 32;

__device__ __half g_qh [NPIX * CH];
__device__ __half g_kh [NPIX * CH];
__device__ __half g_vh [NPIX * CH];
__device__ float  g_att[NPIX * CH];
__device__ float  g_y2 [NPIX * CH];

// ---------------------------------------------------------------------------
// exp2, x <= 0 domain. Round-to-nearest trick (no floor/F2I); Taylor-5 on
// [-0.5, 0.5] (max err ~2.4e-6). Clamps at -126 so masked (-1e30) -> ~0.
__device__ __forceinline__ float fexp2(float x) {
    x = fmaxf(x, -126.0f);
    float r = x + 12582912.0f;            // 1.5*2^23: RN -> integer in low bits
    int   i = __float_as_int(r);
    float f = x - (r - 12582912.0f);      // f in [-0.5, 0.5]
    float p = fmaf(f, 1.3333558e-3f, 9.6181291e-3f);
    p = fmaf(f, p, 5.5504109e-2f);
    p = fmaf(f, p, 2.4022651e-1f);
    p = fmaf(f, p, 6.9314718e-1f);
    p = fmaf(f, p, 1.0f);
    return p * __int_as_float((i + (int)(127 - 0x4B400000)) << 23);
}

// pack two f32 -> f16x2 (lo in low half)
__device__ __forceinline__ unsigned pkh2(float lo, float hi) {
    unsigned r;
    asm("cvt.rn.f16x2.f32 %0, %1, %2;" : "=r"(r) : "f"(hi), "f"(lo));
    return r;
}

__device__ __forceinline__ void mma16h(float& c0, float& c1, float& c2, float& c3,
                                       unsigned a0, unsigned a1, unsigned a2, unsigned a3,
                                       unsigned b0, unsigned b1) {
    asm("mma.sync.aligned.m16n8k16.row.col.f32.f16.f16.f32 "
        "{%0,%1,%2,%3}, {%4,%5,%6,%7}, {%8,%9}, {%0,%1,%2,%3};"
        : "+f"(c0), "+f"(c1), "+f"(c2), "+f"(c3)
        : "r"(a0), "r"(a1), "r"(a2), "r"(a3), "r"(b0), "r"(b1));
}

__device__ __forceinline__ void ldsm4(unsigned& r0, unsigned& r1, unsigned& r2, unsigned& r3,
                                      const void* p) {
    unsigned a = (unsigned)__cvta_generic_to_shared(p);
    asm volatile("ldmatrix.sync.aligned.m8n8.x4.shared.b16 {%0,%1,%2,%3}, [%4];"
                 : "=r"(r0), "=r"(r1), "=r"(r2), "=r"(r3) : "r"(a));
}

__device__ __forceinline__ void ldsm4t(unsigned& r0, unsigned& r1, unsigned& r2, unsigned& r3,
                                       const void* p) {
    unsigned a = (unsigned)__cvta_generic_to_shared(p);
    asm volatile("ldmatrix.sync.aligned.m8n8.x4.trans.shared.b16 {%0,%1,%2,%3}, [%4];"
                 : "=r"(r0), "=r"(r1), "=r"(r2), "=r"(r3) : "r"(a));
}

__device__ __forceinline__ void cpa16(void* dst, const void* src) {
    unsigned d = (unsigned)__cvta_generic_to_shared(dst);
    asm volatile("cp.async.ca.shared.global [%0], [%1], 16;" :: "r"(d), "l"(src));
}

// ---------------------------------------------------------------------------
// Merged QKV GEMM -> fp16 outputs. grid (NPIX/64, 12); y>>2 sel, y&3 -> ob.
// Register-prefetch double buffering on the k-chunks.
__global__ __launch_bounds__(256) void gemm_qkv(
    const float* __restrict__ x,
    const float* __restrict__ Wq, const float* __restrict__ bq,
    const float* __restrict__ Wk, const float* __restrict__ bk,
    const float* __restrict__ Wv, const float* __restrict__ bv)
{
    int sel = blockIdx.y >> 2;
    const float* W    = (sel == 0) ? Wq : (sel == 1) ? Wk : Wv;
    const float* bias = (sel == 0) ? bq : (sel == 1) ? bk : bv;
    __half* Y         = (sel == 0) ? g_qh : (sel == 1) ? g_kh : g_vh;
    const float oscale = (sel == 0) ? (0.17677669529663687f * 1.4426950408889634f) : 1.0f;

    __shared__ float Xs[16][68];
    __shared__ float Wt[16][68];

    int t  = threadIdx.x;
    int nb = blockIdx.x * 64;
    int ob = (blockIdx.y & 3) * 64;
    int nn0 = (t & 15) * 4;
    int oo0 = (t >> 4) * 4;

    int xn = t & 63, xcb = t >> 6;       // X loader: cc = xcb + 4i
    int wc = t & 15, wob = t >> 4;       // W loader: oo = wob + 16i

    float xr[4], wr[4];
    #pragma unroll
    for (int i = 0; i < 4; i++)
        xr[i] = x[(size_t)(xcb + 4 * i) * NPIX + nb + xn];
    #pragma unroll
    for (int i = 0; i < 4; i++)
        wr[i] = W[(size_t)(ob + wob + 16 * i) * CH + wc];

    float acc[4][4] = {};

    for (int cb = 0; cb < CH; cb += 16) {
        __syncthreads();
        #pragma unroll
        for (int i = 0; i < 4; i++) Xs[xcb + 4 * i][xn] = xr[i];
        #pragma unroll
        for (int i = 0; i < 4; i++) Wt[wc][wob + 16 * i] = wr[i];
        __syncthreads();

        if (cb + 16 < CH) {
            #pragma unroll
            for (int i = 0; i < 4; i++)
                xr[i] = x[(size_t)(cb + 16 + xcb + 4 * i) * NPIX + nb + xn];
            #pragma unroll
            for (int i = 0; i < 4; i++)
                wr[i] = W[(size_t)(ob + wob + 16 * i) * CH + cb + 16 + wc];
        }

        #pragma unroll
        for (int cc = 0; cc < 16; cc++) {
            float4 xv = *(const float4*)&Xs[cc][nn0];
            float4 wv = *(const float4*)&Wt[cc][oo0];
            float xe[4] = {xv.x, xv.y, xv.z, xv.w};
            float we[4] = {wv.x, wv.y, wv.z, wv.w};
            #pragma unroll
            for (int i = 0; i < 4; i++)
                #pragma unroll
                for (int j = 0; j < 4; j++)
                    acc[i][j] = fmaf(xe[i], we[j], acc[i][j]);
        }
    }

    float4 bv4 = *(const float4*)&bias[ob + oo0];
    float be[4] = {bv4.x, bv4.y, bv4.z, bv4.w};
    #pragma unroll
    for (int i = 0; i < 4; i++) {
        int n = nb + nn0 + i;
        unsigned h01 = pkh2(oscale * (acc[i][0] + be[0]), oscale * (acc[i][1] + be[1]));
        unsigned h23 = pkh2(oscale * (acc[i][2] + be[2]), oscale * (acc[i][3] + be[3]));
        uint2 pk = {h01, h23};
        *(uint2*)&Y[(size_t)n * CH + ob + oo0] = pk;
    }
}

// Output GEMM with residual: y2[n][o] = sum_c Wo[o][c]*att[n][c] + bo + x[o][n]
__global__ __launch_bounds__(256) void gemm_o(
    const float* __restrict__ W, const float* __restrict__ bias,
    const float* __restrict__ resid)
{
    __shared__ float Xs[16][68];
    __shared__ float Wt[16][68];

    int t  = threadIdx.x;
    int nb = blockIdx.x * 64;
    int ob = blockIdx.y * 64;
    int nn0 = (t & 15) * 4;
    int oo0 = (t >> 4) * 4;

    int xcc = t & 15, xnb = t >> 4;      // X loader: nn = xnb + 16i
    int wc  = t & 15, wob = t >> 4;

    float xr[4], wr[4];
    #pragma unroll
    for (int i = 0; i < 4; i++)
        xr[i] = g_att[(size_t)(nb + xnb + 16 * i) * CH + xcc];
    #pragma unroll
    for (int i = 0; i < 4; i++)
        wr[i] = W[(size_t)(ob + wob + 16 * i) * CH + wc];

    float acc[4][4] = {};

    for (int cb = 0; cb < CH; cb += 16) {
        __syncthreads();
        #pragma unroll
        for (int i = 0; i < 4; i++) Xs[xcc][xnb + 16 * i] = xr[i];
        #pragma unroll
        for (int i = 0; i < 4; i++) Wt[wc][wob + 16 * i] = wr[i];
        __syncthreads();

        if (cb + 16 < CH) {
            #pragma unroll
            for (int i = 0; i < 4; i++)
                xr[i] = g_att[(size_t)(nb + xnb + 16 * i) * CH + cb + 16 + xcc];
            #pragma unroll
            for (int i = 0; i < 4; i++)
                wr[i] = W[(size_t)(ob + wob + 16 * i) * CH + cb + 16 + wc];
        }

        #pragma unroll
        for (int cc = 0; cc < 16; cc++) {
            float4 xv = *(const float4*)&Xs[cc][nn0];
            float4 wv = *(const float4*)&Wt[cc][oo0];
            float xe[4] = {xv.x, xv.y, xv.z, xv.w};
            float we[4] = {wv.x, wv.y, wv.z, wv.w};
            #pragma unroll
            for (int i = 0; i < 4; i++)
                #pragma unroll
                for (int j = 0; j < 4; j++)
                    acc[i][j] = fmaf(xe[i], we[j], acc[i][j]);
        }
    }

    float4 bv = *(const float4*)&bias[ob + oo0];
    float be[4] = {bv.x, bv.y, bv.z, bv.w};
    #pragma unroll
    for (int i = 0; i < 4; i++) {
        int n = nb + nn0 + i;
        float r[4];
        #pragma unroll
        for (int j = 0; j < 4; j++)
            r[j] = acc[i][j] + be[j] + resid[(size_t)(ob + oo0 + j) * NPIX + n];
        float4 rv = {r[0], r[1], r[2], r[3]};
        *(float4*)&g_y2[(size_t)n * CH + ob + oo0] = rv;
    }
}

// ---------------------------------------------------------------------------
// Flash attention, all fp16 mma. CTA: 1 head x 64 q-rows, 4 warps (16 rows each).
// K/V in smem [key][40] half (stride 40 -> conflict-free LDSM), 2-stage cp.async.
__global__ __launch_bounds__(128, 4) void attn_kernel(const int* __restrict__ mask)
{
    __shared__ alignas(16) __half Ksh[2][64][40];
    __shared__ alignas(16) __half Vsh[2][64][40];

    const unsigned F = 0xffffffffu;
    int t    = threadIdx.x;
    int lane = t & 31;
    int w    = t >> 5;
    int h    = blockIdx.y;
    int qb   = blockIdx.x * 64;
    int gr   = lane >> 2;
    int qt   = lane & 3;
    int hoff = h * HD;

    int r_lo = qb + w * 16 + gr;
    int r_hi = r_lo + 8;

    // Q A-fragments (already scaled by qks in GEMM epilogue)
    unsigned qa[2][4];
    {
        const __half* ql = g_qh + (size_t)r_lo * CH + hoff;
        const __half* qh2 = g_qh + (size_t)r_hi * CH + hoff;
        #pragma unroll
        for (int kc = 0; kc < 2; kc++) {
            qa[kc][0] = *(const unsigned*)(ql  + 16 * kc + 2 * qt);
            qa[kc][1] = *(const unsigned*)(qh2 + 16 * kc + 2 * qt);
            qa[kc][2] = *(const unsigned*)(ql  + 16 * kc + 8 + 2 * qt);
            qa[kc][3] = *(const unsigned*)(qh2 + 16 * kc + 8 + 2 * qt);
        }
    }

    // staging: thread -> (key = t/2, half-row hh = t&1); 4x cp.async 16B
    int skey = t >> 1, shh = t & 1;
    const __half* ksrc0 = g_kh + (size_t)skey * CH + hoff + shh * 16;
    const __half* vsrc0 = g_vh + (size_t)skey * CH + hoff + shh * 16;

    float oc[4][4] = {};
    float M0 = -1e30f, M1 = -1e30f, L0 = 0.f, L1 = 0.f;

    const size_t mrow_lo = ((size_t)h * NPIX + r_lo) * NPIX;
    const size_t mrow_hi = ((size_t)h * NPIX + r_hi) * NPIX;

    // prologue: stage block 0 into buffer 0
    {
        cpa16(&Ksh[0][skey][shh * 16],     ksrc0);
        cpa16(&Ksh[0][skey][shh * 16 + 8], ksrc0 + 8);
        cpa16(&Vsh[0][skey][shh * 16],     vsrc0);
        cpa16(&Vsh[0][skey][shh * 16 + 8], vsrc0 + 8);
        asm volatile("cp.async.commit_group;");
    }

    for (int kb = 0; kb < 64; kb++) {
        int b = kb & 1;
        if (kb < 63) {   // stage next block into other buffer (overlaps compute)
            const __half* ks = ksrc0 + (size_t)(kb + 1) * 64 * CH;
            const __half* vs = vsrc0 + (size_t)(kb + 1) * 64 * CH;
            cpa16(&Ksh[b ^ 1][skey][shh * 16],     ks);
            cpa16(&Ksh[b ^ 1][skey][shh * 16 + 8], ks + 8);
            cpa16(&Vsh[b ^ 1][skey][shh * 16],     vs);
            cpa16(&Vsh[b ^ 1][skey][shh * 16 + 8], vs + 8);
            asm volatile("cp.async.commit_group;");
        }

        // mask loads (independent of smem; overlap the wait)
        int2 mw0[8], mw1[8];
        #pragma unroll
        for (int nt = 0; nt < 8; nt++) {
            size_t c = (size_t)(kb * 64 + nt * 8 + 2 * qt);
            mw0[nt] = *(const int2*)(mask + mrow_lo + c);
            mw1[nt] = *(const int2*)(mask + mrow_hi + c);
        }

        if (kb < 63) asm volatile("cp.async.wait_group 1;");
        else         asm volatile("cp.async.wait_group 0;");
        __syncthreads();

        // S = Q K^T  (fp16 m16n8k16, B-frags via ldmatrix)
        float sc[8][4];
        #pragma unroll
        for (int nt = 0; nt < 8; nt++) {
            unsigned r0, r1, r2, r3;
            ldsm4(r0, r1, r2, r3, &Ksh[b][nt * 8 + (lane & 7)][(lane >> 3) * 8]);
            float c0 = 0.f, c1 = 0.f, c2 = 0.f, c3 = 0.f;
            mma16h(c0, c1, c2, c3, qa[0][0], qa[0][1], qa[0][2], qa[0][3], r0, r1);
            mma16h(c0, c1, c2, c3, qa[1][0], qa[1][1], qa[1][2], qa[1][3], r2, r3);
            sc[nt][0] = mw0[nt].x ? c0 : -1e30f;
            sc[nt][1] = mw0[nt].y ? c1 : -1e30f;
            sc[nt][2] = mw1[nt].x ? c2 : -1e30f;
            sc[nt][3] = mw1[nt].y ? c3 : -1e30f;
        }

        // online softmax
        float m_lo = -1e30f, m_hi = -1e30f;
        #pragma unroll
        for (int nt = 0; nt < 8; nt++) {
            m_lo = fmaxf(m_lo, fmaxf(sc[nt][0], sc[nt][1]));
            m_hi = fmaxf(m_hi, fmaxf(sc[nt][2], sc[nt][3]));
        }
        m_lo = fmaxf(m_lo, __shfl_xor_sync(F, m_lo, 1));
        m_lo = fmaxf(m_lo, __shfl_xor_sync(F, m_lo, 2));
        m_hi = fmaxf(m_hi, __shfl_xor_sync(F, m_hi, 1));
        m_hi = fmaxf(m_hi, __shfl_xor_sync(F, m_hi, 2));

        float Mn0 = fmaxf(M0, m_lo), Mn1 = fmaxf(M1, m_hi);
        float a0 = fexp2(M0 - Mn0), a1 = fexp2(M1 - Mn1);
        M0 = Mn0; M1 = Mn1;

        float ls0 = 0.f, ls1 = 0.f;
        #pragma unroll
        for (int nt = 0; nt < 8; nt++) {
            sc[nt][0] = fexp2(sc[nt][0] - M0);   // masked -> ~2^-126 -> fp16 0
            sc[nt][1] = fexp2(sc[nt][1] - M0);
            sc[nt][2] = fexp2(sc[nt][2] - M1);
            sc[nt][3] = fexp2(sc[nt][3] - M1);
            ls0 += sc[nt][0] + sc[nt][1];
            ls1 += sc[nt][2] + sc[nt][3];
        }
        L0 = fmaf(L0, a0, ls0);
        L1 = fmaf(L1, a1, ls1);

        #pragma unroll
        for (int dt = 0; dt < 4; dt++) {
            oc[dt][0] *= a0; oc[dt][1] *= a0;
            oc[dt][2] *= a1; oc[dt][3] *= a1;
        }

        // O += P V  (A straight from S-frags; B via ldmatrix.trans)
        int vrow0 = ((lane >> 3) & 1) * 8 + (lane & 7);
        int vcol0 = ((lane >> 3) >> 1) * 8;
        #pragma unroll
        for (int j = 0; j < 4; j++) {
            unsigned a0u = pkh2(sc[2*j][0],   sc[2*j][1]);
            unsigned a1u = pkh2(sc[2*j][2],   sc[2*j][3]);
            unsigned a2u = pkh2(sc[2*j+1][0], sc[2*j+1][1]);
            unsigned a3u = pkh2(sc[2*j+1][2], sc[2*j+1][3]);
            unsigned b0, b1, b2, b3;
            ldsm4t(b0, b1, b2, b3, &Vsh[b][16 * j + vrow0][vcol0]);
            mma16h(oc[0][0], oc[0][1], oc[0][2], oc[0][3], a0u, a1u, a2u, a3u, b0, b1);
            mma16h(oc[1][0], oc[1][1], oc[1][2], oc[1][3], a0u, a1u, a2u, a3u, b2, b3);
            ldsm4t(b0, b1, b2, b3, &Vsh[b][16 * j + vrow0][16 + vcol0]);
            mma16h(oc[2][0], oc[2][1], oc[2][2], oc[2][3], a0u, a1u, a2u, a3u, b0, b1);
            mma16h(oc[3][0], oc[3][1], oc[3][2], oc[3][3], a0u, a1u, a2u, a3u, b2, b3);
        }

        __syncthreads();   // all warps done with buffer b before it is re-staged
    }

    // finish L reduction across quad (partials disjoint: cols 2qt,2qt+1)
    L0 += __shfl_xor_sync(F, L0, 1);
    L0 += __shfl_xor_sync(F, L0, 2);
    L1 += __shfl_xor_sync(F, L1, 1);
    L1 += __shfl_xor_sync(F, L1, 2);

    float rl0 = 1.0f / L0;
    float rl1 = 1.0f / L1;
    #pragma unroll
    for (int dt = 0; dt < 4; dt++) {
        int cb = hoff + dt * 8 + 2 * qt;
        float2 vlo = { oc[dt][0] * rl0, oc[dt][1] * rl0 };
        float2 vhi = { oc[dt][2] * rl1, oc[dt][3] * rl1 };
        *(float2*)&g_att[(size_t)r_lo * CH + cb] = vlo;
        *(float2*)&g_att[(size_t)r_hi * CH + cb] = vhi;
    }
}

// ---------------------------------------------------------------------------
__global__ __launch_bounds__(256) void ln_kernel(
    const float* __restrict__ gamma, const float* __restrict__ beta,
    float* __restrict__ out)
{
    __shared__ float tile[32][257];
    __shared__ float mu_s[32], rs_s[32];
    const unsigned FULL = 0xffffffffu;

    int t    = threadIdx.x;
    int pb   = blockIdx.x * 32;
    int lane = t & 31;
    int w    = t >> 5;

    #pragma unroll
    for (int i = 0; i < 32; i++)
        tile[i][t] = g_y2[(size_t)(pb + i) * CH + t];
    __syncthreads();

    #pragma unroll
    for (int pi = 0; pi < 4; pi++) {
        int p = w + 8 * pi;
        float sm = 0.f, sq = 0.f;
        #pragma unroll
        for (int c = 0; c < CH; c += 32) {
            float xv = tile[p][c + lane];
            sm += xv;
            sq  = fmaf(xv, xv, sq);
        }
        #pragma unroll
        for (int off = 16; off > 0; off >>= 1) {
            sm += __shfl_xor_sync(FULL, sm, off);
            sq += __shfl_xor_sync(FULL, sq, off);
        }
        if (lane == 0) {
            float mu  = sm * (1.0f / CH);
            float var = sq * (1.0f / CH) - mu * mu;
            mu_s[p] = mu;
            rs_s[p] = rsqrtf(var + 1e-5f);
        }
    }
    __syncthreads();

    float mu = mu_s[lane];
    float rs = rs_s[lane];
    #pragma unroll
    for (int i = 0; i < 32; i++) {
        int c = w + 8 * i;
        float g = gamma[c], b = beta[c];
        out[(size_t)c * NPIX + pb + lane] = (tile[lane][c] - mu) * rs * g + b;
    }
}

// ---------------------------------------------------------------------------
extern "C" void kernel_launch(void* const* d_in, const int* in_sizes, int n_in,
                              void* d_out, int out_size)
{
    const float* x    = (const float*)d_in[0];
    const int*   mask = (const int*)d_in[1];
    const float* Wq = (const float*)d_in[2];
    const float* bq = (const float*)d_in[3];
    const float* Wk = (const float*)d_in[4];
    const float* bk = (const float*)d_in[5];
    const float* Wv = (const float*)d_in[6];
    const float* bv = (const float*)d_in[7];
    const float* Wo = (const float*)d_in[8];
    const float* bo = (const float*)d_in[9];
    const float* gamma = (const float*)d_in[10];
    const float* beta  = (const float*)d_in[11];
    float* out = (float*)d_out;

    gemm_qkv<<<dim3(NPIX / 64, 12), 256>>>(x, Wq, bq, Wk, bk, Wv, bv);
    attn_kernel<<<dim3(NPIX / 64, NH), 128>>>(mask);
    gemm_o<<<dim3(NPIX / 64, CH / 64), 256>>>(Wo, bo, x);
    ln_kernel<<<NPIX / 32, 256>>>(gamma, beta, out);
}